// round 8
// baseline (speedup 1.0000x reference)
#include <cuda_runtime.h>

#define NB 32
#define TT 16384
#define HH 64
#define GG 192         // blockDim: 64 gate + 128 producer threads
#define NBPC 4         // batches per CTA
#define NCTA (NB / NBPC)
#define XCHUNK 64

typedef unsigned long long ull;

// ---- packed f32x2 helpers (Blackwell; only reachable via PTX) ----
__device__ __forceinline__ ull fma2(ull a, ull b, ull c) {
    ull d;
    asm("fma.rn.f32x2 %0, %1, %2, %3;" : "=l"(d) : "l"(a), "l"(b), "l"(c));
    return d;
}
__device__ __forceinline__ ull add2(ull a, ull b) {
    ull d;
    asm("add.rn.f32x2 %0, %1, %2;" : "=l"(d) : "l"(a), "l"(b));
    return d;
}
__device__ __forceinline__ void unpack2(ull v, float& lo, float& hi) {
    asm("mov.b64 {%0, %1}, %2;" : "=f"(lo), "=f"(hi) : "l"(v));
}
__device__ __forceinline__ ull pack2(float lo, float hi) {
    ull v;
    asm("mov.b64 %0, {%1, %2};" : "=l"(v) : "f"(lo), "f"(hi));
    return v;
}

// MUFU.TANH gates — validated rel_err ~2e-6 in R6
__device__ __forceinline__ float tanh_a(float v) {
    float r;
    asm("tanh.approx.f32 %0, %1;" : "=f"(r) : "f"(v));
    return r;
}
__device__ __forceinline__ float sig_a(float v) {
    return fmaf(0.5f, tanh_a(0.5f * v), 0.5f);
}

#define NBAR_SYNC(id, cnt) \
    asm volatile("bar.sync %0, %1;" :: "r"(id), "r"(cnt) : "memory")
#define NBAR_ARRIVE(id, cnt) \
    asm volatile("bar.arrive %0, %1;" :: "r"(id), "r"(cnt) : "memory")

// 4-batch interleaved 64-col dot: 16 independent FMA chains (4 batches x
// 4 accumulators, depth 8) -> latency fully hidden, issue-bound.
__device__ __forceinline__ void dot4(const ull* __restrict__ w,
                                     const float (*hs)[HH],
                                     float bias, float* out) {
    ull a[NBPC][4];
    #pragma unroll
    for (int bb = 0; bb < NBPC; bb++) {
        a[bb][0] = pack2(bias, 0.0f);
        a[bb][1] = 0ull; a[bb][2] = 0ull; a[bb][3] = 0ull;
    }
    #pragma unroll
    for (int j = 0; j < 8; j++) {
        #pragma unroll
        for (int bb = 0; bb < NBPC; bb++) {
            const ulonglong2* hp = (const ulonglong2*)hs[bb];
            ulonglong2 v0 = hp[2 * j];          // broadcast LDS.128
            ulonglong2 v1 = hp[2 * j + 1];
            a[bb][0] = fma2(w[4 * j],     v0.x, a[bb][0]);
            a[bb][1] = fma2(w[4 * j + 1], v0.y, a[bb][1]);
            a[bb][2] = fma2(w[4 * j + 2], v1.x, a[bb][2]);
            a[bb][3] = fma2(w[4 * j + 3], v1.y, a[bb][3]);
        }
    }
    #pragma unroll
    for (int bb = 0; bb < NBPC; bb++) {
        float lo, hi;
        unpack2(add2(add2(a[bb][0], a[bb][1]), add2(a[bb][2], a[bb][3])), lo, hi);
        out[bb] = lo + hi;
    }
}

// ---------------------------------------------------------------------------
// Multi-batch warp-specialized scan. One block handles NBPC=4 batches.
//   threads [0,64):    gate threads — r-dot (x4 batches) + sigmoid locally
//                      (overlapped with producers), then gate tail + h update.
//   threads [64,128):  z producers — publish sigma(z) per batch (sigmoid moved
//                      off the gate critical path into producer slack).
//   threads [128,192): n producers — publish gh_n per batch.
// Barriers: bar1 (zn ready: producers arrive, gates sync, 192)
//           bar3 (h ready: full sync, 192)
// ---------------------------------------------------------------------------
__global__ void __launch_bounds__(GG, 1) gru_scan_kernel(
    const float* __restrict__ x,
    const float* __restrict__ W_ih,
    const float* __restrict__ W_hh,
    const float* __restrict__ b_ih,
    const float* __restrict__ b_hh,
    float* __restrict__ states)
{
    const int b0 = blockIdx.x * NBPC;
    const int g = threadIdx.x;

    __shared__ float h_sh[NBPC][HH];
    __shared__ float2 zn_sh[NBPC][HH];   // .x = sigma(z), .y = gh_n
    __shared__ float x_sh[2][NBPC][XCHUNK];

    // Register-resident W_hh row g (256B, aligned) — shared across batches.
    ull w[32];
    {
        const ulonglong2* wr = (const ulonglong2*)(W_hh + (size_t)g * HH);
        #pragma unroll
        for (int j = 0; j < 16; j++) {
            ulonglong2 v = wr[j];
            w[2 * j]     = v.x;
            w[2 * j + 1] = v.y;
        }
    }
    const float bhh = b_hh[g];

    if (g < HH) {
        #pragma unroll
        for (int bb = 0; bb < NBPC; bb++) {
            h_sh[bb][g] = 0.0f;
            x_sh[0][bb][g] = x[(size_t)(b0 + bb) * TT + g];
        }
    }
    __syncthreads();

    if (g < HH) {
        // ------------------------- gate threads -------------------------
        const float wir = W_ih[g],          bir = b_ih[g];
        const float wiz = W_ih[HH + g],     biz = b_ih[HH + g];
        const float win = W_ih[2 * HH + g], bin = b_ih[2 * HH + g];
        float h[NBPC], xnext[NBPC];
        #pragma unroll
        for (int bb = 0; bb < NBPC; bb++) h[bb] = 0.0f;
        int tmod = 0, buf = 0;

        for (int t = 0; t < TT; t++) {
            if (tmod == 0) {
                int tn = t + XCHUNK;
                if (tn < TT) {
                    #pragma unroll
                    for (int bb = 0; bb < NBPC; bb++)
                        xnext[bb] = x[(size_t)(b0 + bb) * TT + tn + g];
                }
            } else if (tmod == XCHUNK / 2) {
                if (t + XCHUNK / 2 < TT) {
                    #pragma unroll
                    for (int bb = 0; bb < NBPC; bb++)
                        x_sh[buf ^ 1][bb][g] = xnext[bb];
                }
            }

            // r-dots for all batches, overlapped with producers' dots
            float rdot[NBPC];
            dot4(w, h_sh, bhh, rdot);
            float xt[NBPC], r[NBPC], xpz[NBPC], xpn[NBPC];
            #pragma unroll
            for (int bb = 0; bb < NBPC; bb++) {
                xt[bb]  = x_sh[buf][bb][tmod];
                r[bb]   = sig_a(fmaf(xt[bb], wir, bir) + rdot[bb]);
                xpz[bb] = fmaf(xt[bb], wiz, biz);
                xpn[bb] = fmaf(xt[bb], win, bin);
            }

            NBAR_SYNC(1, GG);                    // wait z/n publishes
            #pragma unroll
            for (int bb = 0; bb < NBPC; bb++) {
                const float2 zn = zn_sh[bb][g];  // one LDS.64
                const float z = zn.x;            // already sigma(.)
                const float n = tanh_a(fmaf(r[bb], zn.y, xpn[bb]));
                h[bb] = n + z * (h[bb] - n);     // (1-z)*n + z*h
                h_sh[bb][g] = h[bb];
                states[((size_t)(b0 + bb) * TT + t) * HH + g] = h[bb];
            }
            NBAR_SYNC(3, GG);                    // h visible to all

            if (++tmod == XCHUNK) { tmod = 0; buf ^= 1; }
        }
    } else if (g < 2 * HH) {
        // ------------------------- z producers -------------------------
        const int i = g - HH;
        const float wiz = W_ih[HH + i], biz = b_ih[HH + i];
        float d[NBPC];
        int tmod = 0, buf = 0;
        for (int t = 0; t < TT; t++) {
            dot4(w, h_sh, bhh, d);
            #pragma unroll
            for (int bb = 0; bb < NBPC; bb++) {
                const float xt = x_sh[buf][bb][tmod];
                zn_sh[bb][i].x = sig_a(fmaf(xt, wiz, biz) + d[bb]);
            }
            NBAR_ARRIVE(1, GG);
            NBAR_SYNC(3, GG);
            if (++tmod == XCHUNK) { tmod = 0; buf ^= 1; }
        }
    } else {
        // ------------------------- n producers -------------------------
        const int i = g - 2 * HH;
        float d[NBPC];
        for (int t = 0; t < TT; t++) {
            dot4(w, h_sh, bhh, d);
            #pragma unroll
            for (int bb = 0; bb < NBPC; bb++)
                zn_sh[bb][i].y = d[bb];
            NBAR_ARRIVE(1, GG);
            NBAR_SYNC(3, GG);
        }
    }
}

// ---------------------------------------------------------------------------
// Head: out[b,t] = states[b,t,:].W_out + b_out + x[b,t]. One warp per (b,t).
// ---------------------------------------------------------------------------
__global__ void head_kernel(const float* __restrict__ states,
                            const float* __restrict__ x,
                            const float* __restrict__ W_out,
                            const float* __restrict__ b_out,
                            float* __restrict__ out)
{
    const int lane = threadIdx.x & 31;
    const int warp = (int)((blockIdx.x * blockDim.x + threadIdx.x) >> 5);
    const int nw = (int)((gridDim.x * blockDim.x) >> 5);
    const float w0 = W_out[lane];
    const float w1 = W_out[32 + lane];
    const float bo = b_out[0];
    const long total = (long)NB * TT;
    for (long i = warp; i < total; i += nw) {
        const float* s = states + (size_t)i * HH;
        float p = fmaf(s[lane], w0, s[lane + 32] * w1);
        #pragma unroll
        for (int o = 16; o > 0; o >>= 1)
            p += __shfl_xor_sync(0xffffffffu, p, o);
        if (lane == 0) out[i] = p + bo + x[i];
    }
}

extern "C" void kernel_launch(void* const* d_in, const int* in_sizes, int n_in,
                              void* d_out, int out_size) {
    const float* x     = (const float*)d_in[0];
    const float* W_ih  = (const float*)d_in[1];
    const float* W_hh  = (const float*)d_in[2];
    const float* b_ih  = (const float*)d_in[3];
    const float* b_hh  = (const float*)d_in[4];
    const float* W_out = (const float*)d_in[5];
    const float* b_out = (const float*)d_in[6];

    float* out    = (float*)d_out;              // [B*T]   (tuple elem 0)
    float* states = out + (size_t)NB * TT;      // [B*T*H] (tuple elem 1)

    gru_scan_kernel<<<NCTA, GG>>>(x, W_ih, W_hh, b_ih, b_hh, states);
    head_kernel<<<512, 256>>>(states, x, W_out, b_out, out);
}

// round 9
// speedup vs baseline: 3.0131x; 3.0131x over previous
#include <cuda_runtime.h>

#define NB 32
#define TT 16384
#define HH 64
#define GG 192         // 3*H gate rows; blockDim
#define XCHUNK 64      // x prefetch chunk (== #gate threads)

typedef unsigned long long ull;

// ---- packed f32x2 helpers ----
__device__ __forceinline__ ull fma2(ull a, ull b, ull c) {
    ull d;
    asm("fma.rn.f32x2 %0, %1, %2, %3;" : "=l"(d) : "l"(a), "l"(b), "l"(c));
    return d;
}
__device__ __forceinline__ ull add2(ull a, ull b) {
    ull d;
    asm("add.rn.f32x2 %0, %1, %2;" : "=l"(d) : "l"(a), "l"(b));
    return d;
}
__device__ __forceinline__ void unpack2(ull v, float& lo, float& hi) {
    asm("mov.b64 {%0, %1}, %2;" : "=f"(lo), "=f"(hi) : "l"(v));
}
__device__ __forceinline__ ull pack2(float lo, float hi) {
    ull v;
    asm("mov.b64 %0, {%1, %2};" : "=l"(v) : "f"(lo), "f"(hi));
    return v;
}

// MUFU.TANH gates — validated rel_err ~2e-6 over the full recurrence
__device__ __forceinline__ float tanh_a(float v) {
    float r;
    asm("tanh.approx.f32 %0, %1;" : "=f"(r) : "f"(v));
    return r;
}
__device__ __forceinline__ float sig_a(float v) {
    return fmaf(0.5f, tanh_a(0.5f * v), 0.5f);
}

// named barriers (memory clobber forces smem reload across phases)
#define NBAR_SYNC(id, cnt) \
    asm volatile("bar.sync %0, %1;" :: "r"(id), "r"(cnt) : "memory")
#define NBAR_ARRIVE(id, cnt) \
    asm volatile("bar.arrive %0, %1;" :: "r"(id), "r"(cnt) : "memory")

// 64-wide dot of register-resident packed row w[32] with h_sh.
// 8 accumulators (dep depth 4), bias folded into a0.
__device__ __forceinline__ float dot_h(const ull* w, const float* h_sh,
                                       float bias) {
    const ulonglong2* hp = (const ulonglong2*)h_sh;
    ull a0 = pack2(bias, 0.0f);
    ull a1 = 0ull, a2 = 0ull, a3 = 0ull;
    ull a4 = 0ull, a5 = 0ull, a6 = 0ull, a7 = 0ull;
    #pragma unroll
    for (int j = 0; j < 16; j += 4) {
        ulonglong2 v0 = hp[j];
        ulonglong2 v1 = hp[j + 1];
        ulonglong2 v2 = hp[j + 2];
        ulonglong2 v3 = hp[j + 3];
        a0 = fma2(w[2 * j],     v0.x, a0);
        a1 = fma2(w[2 * j + 1], v0.y, a1);
        a2 = fma2(w[2 * j + 2], v1.x, a2);
        a3 = fma2(w[2 * j + 3], v1.y, a3);
        a4 = fma2(w[2 * j + 4], v2.x, a4);
        a5 = fma2(w[2 * j + 5], v2.y, a5);
        a6 = fma2(w[2 * j + 6], v3.x, a6);
        a7 = fma2(w[2 * j + 7], v3.y, a7);
    }
    float lo, hi;
    unpack2(add2(add2(add2(a0, a1), add2(a2, a3)),
                 add2(add2(a4, a5), add2(a6, a7))), lo, hi);
    return lo + hi;
}

// ---------------------------------------------------------------------------
// Warp-specialized scan (R3 skeleton — measured best). One block per batch.
//   threads [0,64)   : gate threads — r-dot + r-sigmoid locally (overlapped
//                      with producers), then short tail + h update.
//   threads [64,128) : z producers — publish sigma(xpz + gh_z) (sigmoid moved
//                      off the gate critical path into producer slack).
//   threads [128,192): n producers — publish gh_n.
// Barriers: bar1 (zn ready: producers arrive, gates sync, count 192)
//           bar3 (h ready: full sync by all 192)
// ---------------------------------------------------------------------------
__global__ void __launch_bounds__(GG, 1) gru_scan_kernel(
    const float* __restrict__ x,
    const float* __restrict__ W_ih,
    const float* __restrict__ W_hh,
    const float* __restrict__ b_ih,
    const float* __restrict__ b_hh,
    float* __restrict__ states)
{
    const int b = blockIdx.x;
    const int g = threadIdx.x;

    __shared__ float h_sh[HH];
    __shared__ float2 zn_sh[HH];         // .x = sigma(z-pre), .y = gh_n
    __shared__ float x_sh[2][XCHUNK];

    // Register-resident W_hh row g (256B, aligned).
    ull w[32];
    {
        const ulonglong2* wr = (const ulonglong2*)(W_hh + (size_t)g * HH);
        #pragma unroll
        for (int j = 0; j < 16; j++) {
            ulonglong2 v = wr[j];
            w[2 * j]     = v.x;
            w[2 * j + 1] = v.y;
        }
    }
    const float bhh = b_hh[g];

    const float* xb = x + (size_t)b * TT;
    float* st_base = states + (size_t)b * TT * HH;

    if (g < HH) {
        h_sh[g] = 0.0f;
        x_sh[0][g] = xb[g];
    }
    __syncthreads();

    if (g < HH) {
        // ---------------- gate threads ----------------
        const float wir = W_ih[g],          bir = b_ih[g];
        const float win = W_ih[2 * HH + g], bin = b_ih[2 * HH + g];
        float h = 0.0f, xnext = 0.0f;
        int tmod = 0, buf = 0;

        for (int t = 0; t < TT; t++) {
            // x double-buffer: LDG at chunk start, commit mid-chunk
            if (tmod == 0) {
                int tn = t + XCHUNK;
                if (tn < TT) xnext = xb[tn + g];
            } else if (tmod == XCHUNK / 2) {
                if (t + XCHUNK / 2 < TT) x_sh[buf ^ 1][g] = xnext;
            }
            const float xt = x_sh[buf][tmod];

            // r-gate: local dot + MUFU sigmoid, overlapped with producers
            const float r = sig_a(fmaf(xt, wir, bir) + dot_h(w, h_sh, bhh));
            const float xpn = fmaf(xt, win, bin);

            NBAR_SYNC(1, GG);                    // wait z/n publishes
            const float2 zn = zn_sh[g];          // one LDS.64
            const float n = tanh_a(fmaf(r, zn.y, xpn));
            h = n + zn.x * (h - n);              // (1-z)*n + z*h
            h_sh[g] = h;
            st_base[(size_t)t * HH + g] = h;     // coalesced, off-path
            NBAR_SYNC(3, GG);                    // h visible to all

            if (++tmod == XCHUNK) { tmod = 0; buf ^= 1; }
        }
    } else if (g < 2 * HH) {
        // ---------------- z producers ----------------
        const int i = g - HH;
        const float wiz = W_ih[g], biz = b_ih[g];   // row g == HH+i
        int tmod = 0, buf = 0;
        for (int t = 0; t < TT; t++) {
            const float d = dot_h(w, h_sh, bhh);
            const float xt = x_sh[buf][tmod];        // broadcast LDS
            zn_sh[i].x = sig_a(fmaf(xt, wiz, biz) + d);
            NBAR_ARRIVE(1, GG);
            NBAR_SYNC(3, GG);
            if (++tmod == XCHUNK) { tmod = 0; buf ^= 1; }
        }
    } else {
        // ---------------- n producers ----------------
        const int i = g - 2 * HH;
        for (int t = 0; t < TT; t++) {
            zn_sh[i].y = dot_h(w, h_sh, bhh);
            NBAR_ARRIVE(1, GG);
            NBAR_SYNC(3, GG);
        }
    }
}

// ---------------------------------------------------------------------------
// Head: out[b,t] = states[b,t,:].W_out + b_out + x[b,t]. One warp per (b,t).
// ---------------------------------------------------------------------------
__global__ void head_kernel(const float* __restrict__ states,
                            const float* __restrict__ x,
                            const float* __restrict__ W_out,
                            const float* __restrict__ b_out,
                            float* __restrict__ out)
{
    const int lane = threadIdx.x & 31;
    const int warp = (int)((blockIdx.x * blockDim.x + threadIdx.x) >> 5);
    const int nw = (int)((gridDim.x * blockDim.x) >> 5);
    const float w0 = W_out[lane];
    const float w1 = W_out[32 + lane];
    const float bo = b_out[0];
    const long total = (long)NB * TT;
    for (long i = warp; i < total; i += nw) {
        const float* s = states + (size_t)i * HH;
        float p = fmaf(s[lane], w0, s[lane + 32] * w1);
        #pragma unroll
        for (int o = 16; o > 0; o >>= 1)
            p += __shfl_xor_sync(0xffffffffu, p, o);
        if (lane == 0) out[i] = p + bo + x[i];
    }
}

extern "C" void kernel_launch(void* const* d_in, const int* in_sizes, int n_in,
                              void* d_out, int out_size) {
    const float* x     = (const float*)d_in[0];
    const float* W_ih  = (const float*)d_in[1];
    const float* W_hh  = (const float*)d_in[2];
    const float* b_ih  = (const float*)d_in[3];
    const float* b_hh  = (const float*)d_in[4];
    const float* W_out = (const float*)d_in[5];
    const float* b_out = (const float*)d_in[6];

    float* out    = (float*)d_out;              // [B*T]   (tuple elem 0)
    float* states = out + (size_t)NB * TT;      // [B*T*H] (tuple elem 1)

    gru_scan_kernel<<<NB, GG>>>(x, W_ih, W_hh, b_ih, b_hh, states);
    head_kernel<<<512, 256>>>(states, x, W_out, b_out, out);
}